// round 1
// baseline (speedup 1.0000x reference)
#include <cuda_runtime.h>
#include <math.h>

// ---------------- problem constants ----------------
#define B_   32
#define S_   512
#define D_   768
#define H_   12
#define DH   64
#define E_   8
#define DFF  3072
#define T_   (B_*S_)        // 16384 tokens
#define NQKV (3*D_)         // 2304

#define MAX_ROWS (2*T_ + E_*128)   // 33792 padded MoE assignment rows
#define MAX_TILES (MAX_ROWS/128)   // 264

// ---------------- device scratch (static globals; no allocs) ----------------
__device__ float g_x2[T_*D_];                       // LN1 out
__device__ float g_qkv[T_*NQKV];                    // qkv
__device__ float g_scores[B_*H_*S_*S_];             // attention scores (403MB)
__device__ float g_ao[T_*D_];                       // attention context (pre out-proj)
__device__ float g_xm[T_*D_];                       // LN2 out
__device__ float g_h[MAX_ROWS*DFF];                 // MoE hidden (415MB)
__device__ float g_y[MAX_ROWS*D_];                  // MoE expert outputs per slot
__device__ int   g_topi[T_*2];
__device__ float g_topw[T_*2];
__device__ int   g_cnt[E_];
__device__ int   g_off[E_+1];
__device__ int   g_cursor[E_];
__device__ int   g_rowidx[MAX_ROWS];
__device__ float g_rowwt[MAX_ROWS];
__device__ int   g_slot[T_*2];
__device__ int   g_tile_e[MAX_TILES];

// ---------------- LayerNorm (block per row of 768) ----------------
__global__ void ln_kernel(const float* __restrict__ x, const float* __restrict__ gam,
                          const float* __restrict__ bet, float* __restrict__ out) {
    int row = blockIdx.x;
    const float* xr = x + (size_t)row * D_;
    float v[3];
    float s = 0.f, s2 = 0.f;
#pragma unroll
    for (int i = 0; i < 3; i++) {
        v[i] = xr[threadIdx.x + i*256];
        s += v[i]; s2 += v[i]*v[i];
    }
    __shared__ float sh[16];
#pragma unroll
    for (int o = 16; o > 0; o >>= 1) {
        s  += __shfl_down_sync(0xffffffffu, s,  o);
        s2 += __shfl_down_sync(0xffffffffu, s2, o);
    }
    int w = threadIdx.x >> 5, l = threadIdx.x & 31;
    if (l == 0) { sh[w] = s; sh[w+8] = s2; }
    __syncthreads();
    if (threadIdx.x < 32) {
        float a  = (l < 8) ? sh[l]   : 0.f;
        float b2 = (l < 8) ? sh[l+8] : 0.f;
#pragma unroll
        for (int o = 4; o > 0; o >>= 1) {
            a  += __shfl_down_sync(0xffffffffu, a,  o);
            b2 += __shfl_down_sync(0xffffffffu, b2, o);
        }
        if (l == 0) { sh[0] = a; sh[1] = b2; }
    }
    __syncthreads();
    float mean = sh[0] * (1.f/D_);
    float var  = sh[1] * (1.f/D_) - mean*mean;
    float inv  = rsqrtf(var + 1e-5f);
#pragma unroll
    for (int i = 0; i < 3; i++) {
        int c = threadIdx.x + i*256;
        out[(size_t)row*D_ + c] = (v[i] - mean) * inv * gam[c] + bet[c];
    }
}

// ---------------- generic 128x128x8 SGEMM, 256 threads, 8x8 reg tiles -------
// BNK:   B matrix stored [N,K] row-major (weights W, computing A @ W^T)
// !BNK:  B matrix stored [K,N] row-major
// MOE:   row-tile -> expert lookup via g_tile_e; B/bias offset by expert
// GATHER:A row index via g_rowidx (=-1 -> zeros)
// EPI:   0 = +bias; 1 = +bias +resid; 2 = +bias then exact GELU
template<bool BNK, bool MOE, bool GATHER, int EPI>
__global__ void gemm_kernel(const float* __restrict__ A, int lda,
                            const float* __restrict__ Bbase, int ldb, long long bstride,
                            const float* __restrict__ biasbase, int biasstride,
                            const float* __restrict__ resid,
                            float* __restrict__ C, int N, int K)
{
    const float* Bm   = Bbase;
    const float* bias = biasbase;
    if (MOE) {
        int e = g_tile_e[blockIdx.y];
        if (e < 0) return;
        Bm   = Bbase   + (long long)e * bstride;
        bias = biasbase + (long long)e * biasstride;
    }
    int m0 = blockIdx.y * 128, n0 = blockIdx.x * 128;

    __shared__ float As[8][128];
    __shared__ float Bs[8][128];

    int tid = threadIdx.x;
    int tx = tid & 15, ty = tid >> 4;

    // A loader: row = tid>>1 (0..127), 4 consecutive k at (tid&1)*4
    int arow = tid >> 1;
    int ak   = (tid & 1) * 4;
    long long aRow;
    if (GATHER) aRow = g_rowidx[m0 + arow];
    else        aRow = m0 + arow;

    // B loader
    int bn, bk;
    if (BNK) { bn = tid >> 1;  bk = (tid & 1) * 4; }
    else     { bk = tid >> 5;  bn = (tid & 31) * 4; }

    float acc[8][8] = {};

    for (int k0 = 0; k0 < K; k0 += 8) {
        float4 av = make_float4(0.f, 0.f, 0.f, 0.f);
        if (!GATHER || aRow >= 0)
            av = *(const float4*)(A + aRow * (long long)lda + k0 + ak);
        As[ak+0][arow] = av.x; As[ak+1][arow] = av.y;
        As[ak+2][arow] = av.z; As[ak+3][arow] = av.w;

        if (BNK) {
            float4 bv = *(const float4*)(Bm + (long long)(n0 + bn) * ldb + k0 + bk);
            Bs[bk+0][bn] = bv.x; Bs[bk+1][bn] = bv.y;
            Bs[bk+2][bn] = bv.z; Bs[bk+3][bn] = bv.w;
        } else {
            float4 bv = *(const float4*)(Bm + (long long)(k0 + bk) * ldb + n0 + bn);
            *(float4*)&Bs[bk][bn] = bv;
        }
        __syncthreads();

#pragma unroll
        for (int kk = 0; kk < 8; kk++) {
            float a[8], b[8];
#pragma unroll
            for (int i = 0; i < 8; i++) a[i] = As[kk][ty*8 + i];
#pragma unroll
            for (int j = 0; j < 8; j++) b[j] = Bs[kk][tx*8 + j];
#pragma unroll
            for (int i = 0; i < 8; i++)
#pragma unroll
                for (int j = 0; j < 8; j++) acc[i][j] += a[i] * b[j];
        }
        __syncthreads();
    }

#pragma unroll
    for (int i = 0; i < 8; i++) {
        long long row  = m0 + ty*8 + i;
        long long base = row * N + n0 + tx*8;
#pragma unroll
        for (int j = 0; j < 8; j++) {
            float val = acc[i][j] + bias[n0 + tx*8 + j];
            if (EPI == 1) val += resid[base + j];
            if (EPI == 2) val = 0.5f * val * (1.f + erff(val * 0.70710678118654752f));
            C[base + j] = val;
        }
    }
}

// ---------------- attention: scores = Q K^T * 1/8 ----------------
__global__ void attn_scores_kernel(const float* __restrict__ qkv, float* __restrict__ scores)
{
    int bh = blockIdx.z;
    int b = bh / H_, h = bh % H_;
    int q0 = blockIdx.y * 64, k0 = blockIdx.x * 64;
    __shared__ float Qs[64][65], Ks[64][65];
    const float* qbase = qkv + (size_t)(b * S_) * NQKV + h * DH;
    int tid = threadIdx.x;
    for (int f = tid; f < 64*16; f += 256) {
        int r = f >> 4, c4 = (f & 15) * 4;
        float4 qv = *(const float4*)(qbase + (size_t)(q0 + r) * NQKV + c4);
        Qs[r][c4] = qv.x; Qs[r][c4+1] = qv.y; Qs[r][c4+2] = qv.z; Qs[r][c4+3] = qv.w;
        float4 kv = *(const float4*)(qbase + D_ + (size_t)(k0 + r) * NQKV + c4);
        Ks[r][c4] = kv.x; Ks[r][c4+1] = kv.y; Ks[r][c4+2] = kv.z; Ks[r][c4+3] = kv.w;
    }
    __syncthreads();
    int tx = tid & 15, ty = tid >> 4;
    float acc[4][4] = {};
#pragma unroll 8
    for (int kk = 0; kk < 64; kk++) {
        float a[4], bb[4];
#pragma unroll
        for (int i = 0; i < 4; i++) a[i]  = Qs[ty*4 + i][kk];
#pragma unroll
        for (int j = 0; j < 4; j++) bb[j] = Ks[tx*4 + j][kk];
#pragma unroll
        for (int i = 0; i < 4; i++)
#pragma unroll
            for (int j = 0; j < 4; j++) acc[i][j] += a[i] * bb[j];
    }
    float* srow = scores + ((size_t)bh * S_ + q0) * S_ + k0;
#pragma unroll
    for (int i = 0; i < 4; i++)
#pragma unroll
        for (int j = 0; j < 4; j++)
            srow[(size_t)(ty*4 + i) * S_ + tx*4 + j] = acc[i][j] * 0.125f;
}

// ---------------- softmax over last axis (512), block per row ----------------
__global__ void softmax_kernel(float* __restrict__ scores)
{
    size_t row = blockIdx.x;
    float* p = scores + row * S_;
    int tid = threadIdx.x;  // 128
    float v[4];
    float m = -1e30f;
#pragma unroll
    for (int i = 0; i < 4; i++) { v[i] = p[tid + i*128]; m = fmaxf(m, v[i]); }
    __shared__ float sm[4];
#pragma unroll
    for (int o = 16; o > 0; o >>= 1) m = fmaxf(m, __shfl_xor_sync(0xffffffffu, m, o));
    if ((tid & 31) == 0) sm[tid >> 5] = m;
    __syncthreads();
    m = fmaxf(fmaxf(sm[0], sm[1]), fmaxf(sm[2], sm[3]));
    float s = 0.f;
#pragma unroll
    for (int i = 0; i < 4; i++) { v[i] = __expf(v[i] - m); s += v[i]; }
#pragma unroll
    for (int o = 16; o > 0; o >>= 1) s += __shfl_xor_sync(0xffffffffu, s, o);
    __shared__ float ss[4];
    if ((tid & 31) == 0) ss[tid >> 5] = s;
    __syncthreads();
    s = ss[0] + ss[1] + ss[2] + ss[3];
    float inv = 1.f / s;
#pragma unroll
    for (int i = 0; i < 4; i++) p[tid + i*128] = v[i] * inv;
}

// ---------------- attention: context = P @ V ----------------
__global__ void attn_av_kernel(const float* __restrict__ qkv, const float* __restrict__ scores,
                               float* __restrict__ ao)
{
    int bh = blockIdx.y;
    int b = bh / H_, h = bh % H_;
    int s0 = blockIdx.x * 64;
    __shared__ float Ps[64][65], Vs[64][65];
    const float* vbase = qkv + (size_t)(b * S_) * NQKV + 2*D_ + h * DH;
    const float* sbase = scores + ((size_t)bh * S_ + s0) * S_;
    int tid = threadIdx.x, tx = tid & 15, ty = tid >> 4;
    float acc[4][4] = {};
    for (int k0 = 0; k0 < S_; k0 += 64) {
        for (int f = tid; f < 64*16; f += 256) {
            int r = f >> 4, c4 = (f & 15) * 4;
            float4 pv = *(const float4*)(sbase + (size_t)r * S_ + k0 + c4);
            Ps[r][c4] = pv.x; Ps[r][c4+1] = pv.y; Ps[r][c4+2] = pv.z; Ps[r][c4+3] = pv.w;
            float4 vv = *(const float4*)(vbase + (size_t)(k0 + r) * NQKV + c4);
            Vs[r][c4] = vv.x; Vs[r][c4+1] = vv.y; Vs[r][c4+2] = vv.z; Vs[r][c4+3] = vv.w;
        }
        __syncthreads();
#pragma unroll 8
        for (int kk = 0; kk < 64; kk++) {
            float a[4], bb[4];
#pragma unroll
            for (int i = 0; i < 4; i++) a[i]  = Ps[ty*4 + i][kk];
#pragma unroll
            for (int j = 0; j < 4; j++) bb[j] = Vs[kk][tx*4 + j];
#pragma unroll
            for (int i = 0; i < 4; i++)
#pragma unroll
                for (int j = 0; j < 4; j++) acc[i][j] += a[i] * bb[j];
        }
        __syncthreads();
    }
#pragma unroll
    for (int i = 0; i < 4; i++) {
        size_t orow = ((size_t)b * S_ + s0 + ty*4 + i) * D_ + h * DH + tx*4;
#pragma unroll
        for (int j = 0; j < 4; j++) ao[orow + j] = acc[i][j];
    }
}

// ---------------- MoE routing ----------------
__global__ void moe_init_kernel() {
    int i = blockIdx.x * blockDim.x + threadIdx.x;
    if (i < E_) g_cnt[i] = 0;
    if (i < MAX_ROWS) g_rowidx[i] = -1;
}

__global__ void router_kernel(const float* __restrict__ xm, const float* __restrict__ rw,
                              const float* __restrict__ rb)
{
    int t = blockIdx.x;
    int w = threadIdx.x >> 5, l = threadIdx.x & 31;
    const float* xr = xm + (size_t)t * D_;
    const float* wr = rw + (size_t)w * D_;
    float s = 0.f;
    for (int d = l; d < D_; d += 32) s += xr[d] * wr[d];
#pragma unroll
    for (int o = 16; o > 0; o >>= 1) s += __shfl_down_sync(0xffffffffu, s, o);
    __shared__ float sh[E_];
    if (l == 0) sh[w] = s + rb[w];
    __syncthreads();
    if (threadIdx.x == 0) {
        int e1 = 0; float l1 = sh[0];
        for (int e = 1; e < E_; e++) if (sh[e] > l1) { l1 = sh[e]; e1 = e; }
        int e2 = -1; float l2 = -1e30f;
        for (int e = 0; e < E_; e++) if (e != e1 && sh[e] > l2) { l2 = sh[e]; e2 = e; }
        float w1 = 1.f / (1.f + __expf(l2 - l1));
        g_topi[2*t] = e1; g_topi[2*t+1] = e2;
        g_topw[2*t] = w1; g_topw[2*t+1] = 1.f - w1;
        atomicAdd(&g_cnt[e1], 1);
        atomicAdd(&g_cnt[e2], 1);
    }
}

__global__ void scan_kernel() {
    if (threadIdx.x == 0) {
        int o = 0;
        for (int e = 0; e < E_; e++) {
            g_off[e] = o; g_cursor[e] = o;
            o += ((g_cnt[e] + 127) >> 7) << 7;
        }
        g_off[E_] = o;
    }
    __syncthreads();
    for (int t = threadIdx.x; t < MAX_TILES; t += blockDim.x) {
        int row = t << 7;
        int e = -1;
        for (int ee = 0; ee < E_; ee++)
            if (row >= g_off[ee] && row < g_off[ee+1]) e = ee;
        g_tile_e[t] = (row < g_off[E_]) ? e : -1;
    }
}

__global__ void assign_kernel() {
    int t = blockIdx.x * blockDim.x + threadIdx.x;
    if (t >= T_) return;
#pragma unroll
    for (int k = 0; k < 2; k++) {
        int e = g_topi[2*t + k];
        int pos = atomicAdd(&g_cursor[e], 1);
        g_rowidx[pos] = t;
        g_rowwt[pos]  = g_topw[2*t + k];
        g_slot[2*t + k] = pos;
    }
}

__global__ void combine_kernel(float* __restrict__ out) {
    int i = blockIdx.x * blockDim.x + threadIdx.x;  // < T_*D_
    int t = i / D_;
    int d = i - t * D_;
    int s0 = g_slot[2*t], s1 = g_slot[2*t + 1];
    out[i] += g_rowwt[s0] * g_y[(size_t)s0 * D_ + d]
            + g_rowwt[s1] * g_y[(size_t)s1 * D_ + d];
}

// ---------------- launch ----------------
extern "C" void kernel_launch(void* const* d_in, const int* in_sizes, int n_in,
                              void* d_out, int out_size)
{
    const float* x          = (const float*)d_in[0];
    const float* ln1_g      = (const float*)d_in[1];
    const float* ln1_b      = (const float*)d_in[2];
    const float* in_proj_w  = (const float*)d_in[3];
    const float* in_proj_b  = (const float*)d_in[4];
    const float* out_proj_w = (const float*)d_in[5];
    const float* out_proj_b = (const float*)d_in[6];
    const float* ln2_g      = (const float*)d_in[7];
    const float* ln2_b      = (const float*)d_in[8];
    const float* router_w   = (const float*)d_in[9];
    const float* router_b   = (const float*)d_in[10];
    const float* w1         = (const float*)d_in[11];
    const float* b1         = (const float*)d_in[12];
    const float* w2         = (const float*)d_in[13];
    const float* b2         = (const float*)d_in[14];
    float* out = (float*)d_out;

    float *p_x2, *p_qkv, *p_scores, *p_ao, *p_xm, *p_h, *p_y;
    cudaGetSymbolAddress((void**)&p_x2,     g_x2);
    cudaGetSymbolAddress((void**)&p_qkv,    g_qkv);
    cudaGetSymbolAddress((void**)&p_scores, g_scores);
    cudaGetSymbolAddress((void**)&p_ao,     g_ao);
    cudaGetSymbolAddress((void**)&p_xm,     g_xm);
    cudaGetSymbolAddress((void**)&p_h,      g_h);
    cudaGetSymbolAddress((void**)&p_y,      g_y);

    // 1. LN1
    ln_kernel<<<T_, 256>>>(x, ln1_g, ln1_b, p_x2);

    // 2. QKV projection: [T,768] @ [2304,768]^T + b
    gemm_kernel<true, false, false, 0><<<dim3(NQKV/128, T_/128), 256>>>(
        p_x2, D_, in_proj_w, D_, 0, in_proj_b, 0, nullptr, p_qkv, NQKV, D_);

    // 3. scores = Q K^T / 8
    attn_scores_kernel<<<dim3(S_/64, S_/64, B_*H_), 256>>>(p_qkv, p_scores);

    // 4. softmax
    softmax_kernel<<<B_*H_*S_, 128>>>(p_scores);

    // 5. context = P @ V
    attn_av_kernel<<<dim3(S_/64, B_*H_), 256>>>(p_qkv, p_scores, p_ao);

    // 6. out-proj + bias + residual -> d_out holds x after attention
    gemm_kernel<true, false, false, 1><<<dim3(D_/128, T_/128), 256>>>(
        p_ao, D_, out_proj_w, D_, 0, out_proj_b, 0, x, out, D_, D_);

    // 7. LN2
    ln_kernel<<<T_, 256>>>(out, ln2_g, ln2_b, p_xm);

    // 8. routing
    moe_init_kernel<<<(MAX_ROWS + 255)/256, 256>>>();
    router_kernel<<<T_, 256>>>(p_xm, router_w, router_b);
    scan_kernel<<<1, 256>>>();
    assign_kernel<<<(T_ + 255)/256, 256>>>();

    // 9. MoE GEMM1: h = gelu(gather(xm) @ w1[e] + b1[e])
    gemm_kernel<false, true, true, 2><<<dim3(DFF/128, MAX_TILES), 256>>>(
        p_xm, D_, w1, DFF, (long long)D_*DFF, b1, DFF, nullptr, p_h, DFF, D_);

    // 10. MoE GEMM2: y = h @ w2[e] + b2[e]
    gemm_kernel<false, true, false, 0><<<dim3(D_/128, MAX_TILES), 256>>>(
        p_h, DFF, w2, D_, (long long)DFF*D_, b2, D_, nullptr, p_y, D_, DFF);

    // 11. combine: out += w0*y[slot0] + w1*y[slot1]
    combine_kernel<<<(T_*D_)/256, 256>>>(out);
}

// round 3
// speedup vs baseline: 2.3769x; 2.3769x over previous
#include <cuda_runtime.h>
#include <math.h>

// ---------------- problem constants ----------------
#define B_   32
#define S_   512
#define D_   768
#define H_   12
#define DH   64
#define E_   8
#define DFF  3072
#define T_   (B_*S_)        // 16384 tokens
#define NQKV (3*D_)         // 2304

#define MAX_ROWS (2*T_ + E_*128)   // 33792 padded MoE assignment rows
#define MAX_TILES (MAX_ROWS/128)   // 264

// ---------------- device scratch (static globals; no allocs) ----------------
__device__ float g_x2[T_*D_];
__device__ float g_qkv[T_*NQKV];
__device__ float g_scores[B_*H_*S_*S_];
__device__ float g_ao[T_*D_];
__device__ float g_xm[T_*D_];
__device__ float g_h[MAX_ROWS*DFF];
__device__ float g_y[MAX_ROWS*D_];
__device__ int   g_topi[T_*2];
__device__ float g_topw[T_*2];
__device__ int   g_cnt[E_];
__device__ int   g_off[E_+1];
__device__ int   g_cursor[E_];
__device__ int   g_rowidx[MAX_ROWS];
__device__ float g_rowwt[MAX_ROWS];
__device__ int   g_slot[T_*2];
__device__ int   g_tile_e[MAX_TILES];

// ---------------- helpers ----------------
__device__ __forceinline__ unsigned f2tf32(float x) {
    unsigned u;
    asm("cvt.rna.tf32.f32 %0, %1;" : "=r"(u) : "f"(x));
    return u;
}

__device__ __forceinline__ void mma_tf32(float c[4], const unsigned a[4], const unsigned b[2]) {
    asm volatile(
        "mma.sync.aligned.m16n8k8.row.col.f32.tf32.tf32.f32 "
        "{%0,%1,%2,%3}, {%4,%5,%6,%7}, {%8,%9}, {%0,%1,%2,%3};"
        : "+f"(c[0]), "+f"(c[1]), "+f"(c[2]), "+f"(c[3])
        : "r"(a[0]), "r"(a[1]), "r"(a[2]), "r"(a[3]), "r"(b[0]), "r"(b[1]));
}

// ---------------- LayerNorm (block per row of 768) ----------------
__global__ void ln_kernel(const float* __restrict__ x, const float* __restrict__ gam,
                          const float* __restrict__ bet, float* __restrict__ out) {
    int row = blockIdx.x;
    const float* xr = x + (size_t)row * D_;
    float v[3];
    float s = 0.f, s2 = 0.f;
#pragma unroll
    for (int i = 0; i < 3; i++) {
        v[i] = xr[threadIdx.x + i*256];
        s += v[i]; s2 += v[i]*v[i];
    }
    __shared__ float sh[16];
#pragma unroll
    for (int o = 16; o > 0; o >>= 1) {
        s  += __shfl_down_sync(0xffffffffu, s,  o);
        s2 += __shfl_down_sync(0xffffffffu, s2, o);
    }
    int w = threadIdx.x >> 5, l = threadIdx.x & 31;
    if (l == 0) { sh[w] = s; sh[w+8] = s2; }
    __syncthreads();
    if (threadIdx.x < 32) {
        float a  = (l < 8) ? sh[l]   : 0.f;
        float b2 = (l < 8) ? sh[l+8] : 0.f;
#pragma unroll
        for (int o = 4; o > 0; o >>= 1) {
            a  += __shfl_down_sync(0xffffffffu, a,  o);
            b2 += __shfl_down_sync(0xffffffffu, b2, o);
        }
        if (l == 0) { sh[0] = a; sh[1] = b2; }
    }
    __syncthreads();
    float mean = sh[0] * (1.f/D_);
    float var  = sh[1] * (1.f/D_) - mean*mean;
    float inv  = rsqrtf(var + 1e-5f);
#pragma unroll
    for (int i = 0; i < 3; i++) {
        int c = threadIdx.x + i*256;
        out[(size_t)row*D_ + c] = (v[i] - mean) * inv * gam[c] + bet[c];
    }
}

// =====================================================================
// Generic tf32 tensor-core GEMM.
// Block tile: 128 x BN, K-chunk 16, double-buffered smem, 256 threads.
// 8 warps laid out 2 (M) x 4 (N): warp tile 64 x (BN/4).
// mma.sync m16n8k8: per warp 4 m-tiles x WNT n-tiles.
//
// BNK:    B stored [N,K] row-major (computing A @ B^T)
// MOE:    blockIdx.y tile -> expert via g_tile_e (skip if -1)
// GATHER: A row via g_rowidx (-1 -> zero row)
// EPI:    0 +bias | 1 +bias+resid | 2 +bias,GELU | 3 *scale | 4 plain
// ATT:    0 none | 1 scores (A=Q,B=K from qkv, C=scores) | 2 AV (A=scores,B=V,C=ao)
// =====================================================================
template<int BN, bool BNK, bool MOE, bool GATHER, int EPI, int ATT>
__global__ void __launch_bounds__(256) mma_gemm(
    const float* __restrict__ A, int lda,
    const float* __restrict__ Bb, int ldb, long long bstride,
    const float* __restrict__ biasb, int biasstride,
    const float* __restrict__ resid,
    float* __restrict__ C, int ldc, int K, float scale)
{
    constexpr int WN  = BN / 4;
    constexpr int WNT = WN / 8;
    constexpr int LDA_S = 132;
    constexpr int LDB_S = BN + 4;

    __shared__ __align__(16) unsigned As[2][16][LDA_S];
    __shared__ __align__(16) unsigned Bs[2][16][LDB_S];

    int tid  = threadIdx.x;
    int lane = tid & 31, w = tid >> 5;
    int gid  = lane >> 2, tig = lane & 3;
    int wm   = w & 1, wn = w >> 1;
    int m0   = blockIdx.y * 128, n0 = blockIdx.x * BN;

    const float* bias = biasb;
    if (MOE) {
        int e = g_tile_e[blockIdx.y];
        if (e < 0) return;
        Bb   = Bb   + (long long)e * bstride;
        bias = biasb + (long long)e * biasstride;
    }
    if (ATT == 1) {
        int z = blockIdx.z, b = z / H_, h = z % H_;
        A  += (size_t)(b * S_) * NQKV + h * DH;
        Bb += (size_t)(b * S_) * NQKV + D_ + h * DH;
        C  += (size_t)z * S_ * S_;
    }
    if (ATT == 2) {
        int z = blockIdx.z, b = z / H_, h = z % H_;
        A  += (size_t)z * S_ * S_;
        Bb += (size_t)(b * S_) * NQKV + 2 * D_ + h * DH;
        C  += (size_t)(b * S_) * D_ + h * DH;
    }

    // --- A loader mapping: slot f -> row f>>2, 4 k-floats at (f&3)*4
    int ar0 = tid >> 2, ak0 = (tid & 3) * 4;
    long long arow0, arow1;
    if (GATHER) { arow0 = g_rowidx[m0 + ar0]; arow1 = g_rowidx[m0 + ar0 + 64]; }
    else        { arow0 = m0 + ar0;           arow1 = m0 + ar0 + 64; }

    // --- B loader mapping
    int bn0_t, bk0_t;
    if (BNK) { bn0_t = tid >> 2;        bk0_t = (tid & 3) * 4; }
    else     { bk0_t = tid / (BN / 4);  bn0_t = (tid % (BN / 4)) * 4; }
    constexpr int BCNT = BN / 64;   // B float4 loads per thread (!BNK); BNK always 2

    float4 rA0, rA1, rB0, rB1;

    auto loadA = [&](int k0) {
        rA0 = make_float4(0.f, 0.f, 0.f, 0.f);
        rA1 = make_float4(0.f, 0.f, 0.f, 0.f);
        if (!GATHER || arow0 >= 0) rA0 = *(const float4*)(A + arow0 * (long long)lda + k0 + ak0);
        if (!GATHER || arow1 >= 0) rA1 = *(const float4*)(A + arow1 * (long long)lda + k0 + ak0);
    };
    auto stsA = [&](int buf) {
        As[buf][ak0+0][ar0] = f2tf32(rA0.x); As[buf][ak0+1][ar0] = f2tf32(rA0.y);
        As[buf][ak0+2][ar0] = f2tf32(rA0.z); As[buf][ak0+3][ar0] = f2tf32(rA0.w);
        As[buf][ak0+0][ar0+64] = f2tf32(rA1.x); As[buf][ak0+1][ar0+64] = f2tf32(rA1.y);
        As[buf][ak0+2][ar0+64] = f2tf32(rA1.z); As[buf][ak0+3][ar0+64] = f2tf32(rA1.w);
    };
    auto loadB = [&](int k0) {
        if (BNK) {
            rB0 = *(const float4*)(Bb + (long long)(n0 + bn0_t) * ldb + k0 + bk0_t);
            rB1 = *(const float4*)(Bb + (long long)(n0 + bn0_t + 64) * ldb + k0 + bk0_t);
        } else {
            rB0 = *(const float4*)(Bb + (long long)(k0 + bk0_t) * ldb + n0 + bn0_t);
            if (BCNT == 2)
                rB1 = *(const float4*)(Bb + (long long)(k0 + bk0_t + 8) * ldb + n0 + bn0_t);
        }
    };
    auto stsB = [&](int buf) {
        if (BNK) {
            Bs[buf][bk0_t+0][bn0_t] = f2tf32(rB0.x); Bs[buf][bk0_t+1][bn0_t] = f2tf32(rB0.y);
            Bs[buf][bk0_t+2][bn0_t] = f2tf32(rB0.z); Bs[buf][bk0_t+3][bn0_t] = f2tf32(rB0.w);
            Bs[buf][bk0_t+0][bn0_t+64] = f2tf32(rB1.x); Bs[buf][bk0_t+1][bn0_t+64] = f2tf32(rB1.y);
            Bs[buf][bk0_t+2][bn0_t+64] = f2tf32(rB1.z); Bs[buf][bk0_t+3][bn0_t+64] = f2tf32(rB1.w);
        } else {
            uint4 u0; u0.x = f2tf32(rB0.x); u0.y = f2tf32(rB0.y); u0.z = f2tf32(rB0.z); u0.w = f2tf32(rB0.w);
            *(uint4*)&Bs[buf][bk0_t][bn0_t] = u0;
            if (BCNT == 2) {
                uint4 u1; u1.x = f2tf32(rB1.x); u1.y = f2tf32(rB1.y); u1.z = f2tf32(rB1.z); u1.w = f2tf32(rB1.w);
                *(uint4*)&Bs[buf][bk0_t+8][bn0_t] = u1;
            }
        }
    };

    float acc[4][WNT][4];
#pragma unroll
    for (int i = 0; i < 4; i++)
#pragma unroll
        for (int j = 0; j < WNT; j++)
#pragma unroll
            for (int q = 0; q < 4; q++) acc[i][j][q] = 0.f;

    int niter = K / 16;
    loadA(0); loadB(0);
    stsA(0);  stsB(0);
    __syncthreads();

    for (int it = 0; it < niter; it++) {
        int buf = it & 1;
        if (it + 1 < niter) { loadA((it+1)*16); loadB((it+1)*16); }

#pragma unroll
        for (int ks = 0; ks < 16; ks += 8) {
            unsigned af[4][4];
#pragma unroll
            for (int i = 0; i < 4; i++) {
                int m = wm*64 + i*16 + gid;
                af[i][0] = As[buf][ks+tig  ][m];
                af[i][1] = As[buf][ks+tig  ][m+8];
                af[i][2] = As[buf][ks+tig+4][m];
                af[i][3] = As[buf][ks+tig+4][m+8];
            }
            unsigned bf[WNT][2];
#pragma unroll
            for (int j = 0; j < WNT; j++) {
                int n = wn*WN + j*8 + gid;
                bf[j][0] = Bs[buf][ks+tig  ][n];
                bf[j][1] = Bs[buf][ks+tig+4][n];
            }
#pragma unroll
            for (int i = 0; i < 4; i++)
#pragma unroll
                for (int j = 0; j < WNT; j++)
                    mma_tf32(acc[i][j], af[i], bf[j]);
        }

        if (it + 1 < niter) {
            stsA(buf ^ 1); stsB(buf ^ 1);
            __syncthreads();
        }
    }

    // --- epilogue ---
#pragma unroll
    for (int i = 0; i < 4; i++) {
        long long r0 = m0 + wm*64 + i*16 + gid;
        long long r1 = r0 + 8;
#pragma unroll
        for (int j = 0; j < WNT; j++) {
            int c = n0 + wn*WN + j*8 + 2*tig;
            float v00 = acc[i][j][0], v01 = acc[i][j][1];
            float v10 = acc[i][j][2], v11 = acc[i][j][3];
            if (EPI == 0 || EPI == 1 || EPI == 2) {
                float b0 = bias[c], b1 = bias[c+1];
                v00 += b0; v01 += b1; v10 += b0; v11 += b1;
            }
            if (EPI == 1) {
                v00 += resid[r0*ldc + c];   v01 += resid[r0*ldc + c+1];
                v10 += resid[r1*ldc + c];   v11 += resid[r1*ldc + c+1];
            }
            if (EPI == 2) {
                v00 = 0.5f*v00*(1.f + erff(v00*0.70710678118654752f));
                v01 = 0.5f*v01*(1.f + erff(v01*0.70710678118654752f));
                v10 = 0.5f*v10*(1.f + erff(v10*0.70710678118654752f));
                v11 = 0.5f*v11*(1.f + erff(v11*0.70710678118654752f));
            }
            if (EPI == 3) { v00 *= scale; v01 *= scale; v10 *= scale; v11 *= scale; }
            C[r0*ldc + c]   = v00; C[r0*ldc + c+1] = v01;
            C[r1*ldc + c]   = v10; C[r1*ldc + c+1] = v11;
        }
    }
}

// ---------------- softmax over last axis (512), block per row ----------------
__global__ void softmax_kernel(float* __restrict__ scores)
{
    size_t row = blockIdx.x;
    float* p = scores + row * S_;
    int tid = threadIdx.x;  // 128
    float v[4];
    float m = -1e30f;
#pragma unroll
    for (int i = 0; i < 4; i++) { v[i] = p[tid + i*128]; m = fmaxf(m, v[i]); }
    __shared__ float sm[4];
#pragma unroll
    for (int o = 16; o > 0; o >>= 1) m = fmaxf(m, __shfl_xor_sync(0xffffffffu, m, o));
    if ((tid & 31) == 0) sm[tid >> 5] = m;
    __syncthreads();
    m = fmaxf(fmaxf(sm[0], sm[1]), fmaxf(sm[2], sm[3]));
    float s = 0.f;
#pragma unroll
    for (int i = 0; i < 4; i++) { v[i] = __expf(v[i] - m); s += v[i]; }
#pragma unroll
    for (int o = 16; o > 0; o >>= 1) s += __shfl_xor_sync(0xffffffffu, s, o);
    __shared__ float ss[4];
    if ((tid & 31) == 0) ss[tid >> 5] = s;
    __syncthreads();
    s = ss[0] + ss[1] + ss[2] + ss[3];
    float inv = 1.f / s;
#pragma unroll
    for (int i = 0; i < 4; i++) p[tid + i*128] = v[i] * inv;
}

// ---------------- MoE routing ----------------
__global__ void moe_init_kernel() {
    int i = blockIdx.x * blockDim.x + threadIdx.x;
    if (i < E_) g_cnt[i] = 0;
    if (i < MAX_ROWS) g_rowidx[i] = -1;
}

__global__ void router_kernel(const float* __restrict__ xm, const float* __restrict__ rw,
                              const float* __restrict__ rb)
{
    int t = blockIdx.x;
    int w = threadIdx.x >> 5, l = threadIdx.x & 31;
    const float* xr = xm + (size_t)t * D_;
    const float* wr = rw + (size_t)w * D_;
    float s = 0.f;
    for (int d = l; d < D_; d += 32) s += xr[d] * wr[d];
#pragma unroll
    for (int o = 16; o > 0; o >>= 1) s += __shfl_down_sync(0xffffffffu, s, o);
    __shared__ float sh[E_];
    if (l == 0) sh[w] = s + rb[w];
    __syncthreads();
    if (threadIdx.x == 0) {
        int e1 = 0; float l1 = sh[0];
        for (int e = 1; e < E_; e++) if (sh[e] > l1) { l1 = sh[e]; e1 = e; }
        int e2 = -1; float l2 = -1e30f;
        for (int e = 0; e < E_; e++) if (e != e1 && sh[e] > l2) { l2 = sh[e]; e2 = e; }
        float w1 = 1.f / (1.f + __expf(l2 - l1));
        g_topi[2*t] = e1; g_topi[2*t+1] = e2;
        g_topw[2*t] = w1; g_topw[2*t+1] = 1.f - w1;
        atomicAdd(&g_cnt[e1], 1);
        atomicAdd(&g_cnt[e2], 1);
    }
}

__global__ void scan_kernel() {
    if (threadIdx.x == 0) {
        int o = 0;
        for (int e = 0; e < E_; e++) {
            g_off[e] = o; g_cursor[e] = o;
            o += ((g_cnt[e] + 127) >> 7) << 7;
        }
        g_off[E_] = o;
    }
    __syncthreads();
    for (int t = threadIdx.x; t < MAX_TILES; t += blockDim.x) {
        int row = t << 7;
        int e = -1;
        for (int ee = 0; ee < E_; ee++)
            if (row >= g_off[ee] && row < g_off[ee+1]) e = ee;
        g_tile_e[t] = (row < g_off[E_]) ? e : -1;
    }
}

__global__ void assign_kernel() {
    int t = blockIdx.x * blockDim.x + threadIdx.x;
    if (t >= T_) return;
#pragma unroll
    for (int k = 0; k < 2; k++) {
        int e = g_topi[2*t + k];
        int pos = atomicAdd(&g_cursor[e], 1);
        g_rowidx[pos] = t;
        g_rowwt[pos]  = g_topw[2*t + k];
        g_slot[2*t + k] = pos;
    }
}

__global__ void combine_kernel(float* __restrict__ out) {
    int i = blockIdx.x * blockDim.x + threadIdx.x;  // < T_*D_
    int t = i / D_;
    int d = i - t * D_;
    int s0 = g_slot[2*t], s1 = g_slot[2*t + 1];
    out[i] += g_rowwt[s0] * g_y[(size_t)s0 * D_ + d]
            + g_rowwt[s1] * g_y[(size_t)s1 * D_ + d];
}

// ---------------- launch ----------------
extern "C" void kernel_launch(void* const* d_in, const int* in_sizes, int n_in,
                              void* d_out, int out_size)
{
    const float* x          = (const float*)d_in[0];
    const float* ln1_g      = (const float*)d_in[1];
    const float* ln1_b      = (const float*)d_in[2];
    const float* in_proj_w  = (const float*)d_in[3];
    const float* in_proj_b  = (const float*)d_in[4];
    const float* out_proj_w = (const float*)d_in[5];
    const float* out_proj_b = (const float*)d_in[6];
    const float* ln2_g      = (const float*)d_in[7];
    const float* ln2_b      = (const float*)d_in[8];
    const float* router_w   = (const float*)d_in[9];
    const float* router_b   = (const float*)d_in[10];
    const float* w1         = (const float*)d_in[11];
    const float* b1         = (const float*)d_in[12];
    const float* w2         = (const float*)d_in[13];
    const float* b2         = (const float*)d_in[14];
    float* out = (float*)d_out;

    float *p_x2, *p_qkv, *p_scores, *p_ao, *p_xm, *p_h, *p_y;
    cudaGetSymbolAddress((void**)&p_x2,     g_x2);
    cudaGetSymbolAddress((void**)&p_qkv,    g_qkv);
    cudaGetSymbolAddress((void**)&p_scores, g_scores);
    cudaGetSymbolAddress((void**)&p_ao,     g_ao);
    cudaGetSymbolAddress((void**)&p_xm,     g_xm);
    cudaGetSymbolAddress((void**)&p_h,      g_h);
    cudaGetSymbolAddress((void**)&p_y,      g_y);

    // 1. LN1
    ln_kernel<<<T_, 256>>>(x, ln1_g, ln1_b, p_x2);

    // 2. QKV projection: [T,768] @ [2304,768]^T + b
    mma_gemm<128, true, false, false, 0, 0><<<dim3(NQKV/128, T_/128), 256>>>(
        p_x2, D_, in_proj_w, D_, 0, in_proj_b, 0, nullptr, p_qkv, NQKV, D_, 1.f);

    // 3. scores = Q K^T / 8
    mma_gemm<128, true, false, false, 3, 1><<<dim3(S_/128, S_/128, B_*H_), 256>>>(
        p_qkv, NQKV, p_qkv, NQKV, 0, nullptr, 0, nullptr, p_scores, S_, DH, 0.125f);

    // 4. softmax
    softmax_kernel<<<B_*H_*S_, 128>>>(p_scores);

    // 5. context = P @ V
    mma_gemm<64, false, false, false, 4, 2><<<dim3(1, S_/128, B_*H_), 256>>>(
        p_scores, S_, p_qkv, NQKV, 0, nullptr, 0, nullptr, p_ao, D_, S_, 1.f);

    // 6. out-proj + bias + residual -> d_out holds x after attention
    mma_gemm<128, true, false, false, 1, 0><<<dim3(D_/128, T_/128), 256>>>(
        p_ao, D_, out_proj_w, D_, 0, out_proj_b, 0, x, out, D_, D_, 1.f);

    // 7. LN2
    ln_kernel<<<T_, 256>>>(out, ln2_g, ln2_b, p_xm);

    // 8. routing
    moe_init_kernel<<<(MAX_ROWS + 255)/256, 256>>>();
    router_kernel<<<T_, 256>>>(p_xm, router_w, router_b);
    scan_kernel<<<1, 256>>>();
    assign_kernel<<<(T_ + 255)/256, 256>>>();

    // 9. MoE GEMM1: h = gelu(gather(xm) @ w1[e] + b1[e])
    mma_gemm<128, false, true, true, 2, 0><<<dim3(DFF/128, MAX_TILES), 256>>>(
        p_xm, D_, w1, DFF, (long long)D_*DFF, b1, DFF, nullptr, p_h, DFF, D_, 1.f);

    // 10. MoE GEMM2: y = h @ w2[e] + b2[e]
    mma_gemm<128, false, true, false, 0, 0><<<dim3(D_/128, MAX_TILES), 256>>>(
        p_h, DFF, w2, D_, (long long)DFF*D_, b2, D_, nullptr, p_y, D_, DFF, 1.f);

    // 11. combine: out += w0*y[slot0] + w1*y[slot1]
    combine_kernel<<<(T_*D_)/256, 256>>>(out);
}